// round 16
// baseline (speedup 1.0000x reference)
#include <cuda_runtime.h>
#include <cuda_fp16.h>
#include <cstdint>

#define NN 100000
#define DIM 64
#define NREL 16
#define EMAX 1000000
#define TM 128
#define IDS_CAP (EMAX + NREL * TM)

__device__ float g_neighbor[NN * DIM];
__device__ int   g_ids[IDS_CAP];
__device__ int   g_cnt[NREL];
__device__ int   g_off[NREL + 1];
__device__ int   g_cursor[NREL];
__device__ uint4 g_xs[NN * 8];         // per node: 64 fp16 (128B)

// ---------------- smem byte map (edge kernel) ----------------
#define SM_W0   0                      // W fp16 [64k][64n] swizzled (8192)
#define SM_A    8192                   // A: buf0, buf1 fp16 (2 x 16384)
#define SM_RE   40960                  // 64 f32
#define SM_ATT  41216                  // 2 x 128 x 2 f32
#define SM_SRC  43264                  // 2 x 128 int
#define SM_DST  44288                  // 2 x 128 int
#define SM_OFF  45312                  // 17 int (+pad)
#define SM_EDGE_TOTAL 45440

// named barriers (384 threads):
//   1,2 = A-full[b]  (mem 128 arrive, compute 256 sync)
//   3,4 = A-free[b]  (compute 256 arrive, mem 128 sync)
//   5   = compute-internal W reload (256)
//   6   = compute-internal epilogue->scatter (256)
#define BAR_SYNC(id)   asm volatile("bar.sync %0, 384;"   :: "r"(id) : "memory")
#define BAR_ARRIVE(id) asm volatile("bar.arrive %0, 384;" :: "r"(id) : "memory")
#define BAR_SYNC_C(id) asm volatile("bar.sync %0, 256;"   :: "r"(id) : "memory")

static __device__ __forceinline__ uint32_t smem_u32(const void* p) {
    uint32_t a;
    asm("{ .reg .u64 t; cvta.to.shared.u64 t, %1; cvt.u32.u64 %0, t; }" : "=r"(a) : "l"(p));
    return a;
}

// ---------- mma.sync / ldmatrix helpers ----------
__device__ __forceinline__ void ldm_a(uint32_t* r, uint32_t base, int m0, int kt, int lane) {
    int row   = m0 + (lane & 15);
    int chunk = (kt << 1) + (lane >> 4);
    uint32_t addr = base + row * 128 + ((chunk ^ (row & 7)) << 4);
    asm volatile("ldmatrix.sync.aligned.m8n8.x4.shared.b16 {%0,%1,%2,%3}, [%4];"
                 : "=r"(r[0]), "=r"(r[1]), "=r"(r[2]), "=r"(r[3]) : "r"(addr));
}
__device__ __forceinline__ void ldm_b(uint32_t* r, uint32_t base, int np, int kt, int lane) {
    int g = lane >> 3;
    int k = (kt << 4) + ((g & 1) << 3) + (lane & 7);
    int nchunk = (np << 1) + (g >> 1);
    uint32_t addr = base + k * 128 + ((nchunk ^ (k & 7)) << 4);
    asm volatile("ldmatrix.sync.aligned.m8n8.x4.trans.shared.b16 {%0,%1,%2,%3}, [%4];"
                 : "=r"(r[0]), "=r"(r[1]), "=r"(r[2]), "=r"(r[3]) : "r"(addr));
}
__device__ __forceinline__ void mma16816(float* d, const uint32_t* a, uint32_t b0, uint32_t b1) {
    asm volatile("mma.sync.aligned.m16n8k16.row.col.f32.f16.f16.f32 "
                 "{%0,%1,%2,%3}, {%4,%5,%6,%7}, {%8,%9}, {%0,%1,%2,%3};"
                 : "+f"(d[0]), "+f"(d[1]), "+f"(d[2]), "+f"(d[3])
                 : "r"(a[0]), "r"(a[1]), "r"(a[2]), "r"(a[3]), "r"(b0), "r"(b1));
}

// ---------- misc helpers ----------
__device__ __forceinline__ void fma2(unsigned long long& d, unsigned long long a, unsigned long long b) {
    asm("fma.rn.f32x2 %0, %1, %2, %0;" : "+l"(d) : "l"(a), "l"(b));
}
__device__ __forceinline__ float2 unpack2(unsigned long long v) {
    float2 r;
    r.x = __uint_as_float((unsigned)(v & 0xffffffffull));
    r.y = __uint_as_float((unsigned)(v >> 32));
    return r;
}
__device__ __forceinline__ unsigned long long pack2(float x, float y) {
    unsigned long long r;
    asm("mov.b64 %0, {%1, %2};" : "=l"(r) : "f"(x), "f"(y));
    return r;
}
__device__ __forceinline__ float tanh_f(float x) {
    float y;
    asm("tanh.approx.f32 %0, %1;" : "=f"(y) : "f"(x));
    return y;
}
__device__ __forceinline__ void red_add_v4(float* addr, float a, float b, float c, float d) {
    asm volatile("red.global.add.v4.f32 [%0], {%1, %2, %3, %4};"
                 :: "l"(addr), "f"(a), "f"(b), "f"(c), "f"(d) : "memory");
}
__device__ __forceinline__ uint32_t pack_h2(float a, float b) {
    unsigned short s0 = __half_as_ushort(__float2half_rn(a));
    unsigned short s1 = __half_as_ushort(__float2half_rn(b));
    return (uint32_t)s0 | ((uint32_t)s1 << 16);
}
__device__ __forceinline__ float h_lo(uint32_t u) {
    return __half2float(__ushort_as_half((unsigned short)(u & 0xffff)));
}
__device__ __forceinline__ float h_hi(uint32_t u) {
    return __half2float(__ushort_as_half((unsigned short)(u >> 16)));
}

// ---------- launch 0: init + histogram + entity fp16 table ----------
__global__ __launch_bounds__(256) void init_hist_kernel(const float* __restrict__ entity,
                                                        const int* __restrict__ etype,
                                                        int E, int n4neigh, int nf4) {
    __shared__ int h[NREL];
    if (threadIdx.x < NREL) h[threadIdx.x] = 0;
    __syncthreads();
    int gtid = blockIdx.x * blockDim.x + threadIdx.x;
    int stride = gridDim.x * blockDim.x;
    if (gtid < NREL) g_cnt[gtid] = 0;
    for (int i = gtid; i < n4neigh; i += stride)
        ((float4*)g_neighbor)[i] = make_float4(0.f, 0.f, 0.f, 0.f);
    uint2* xs2 = (uint2*)g_xs;
    for (int i = gtid; i < nf4; i += stride) {
        int node = i >> 4, qq = i & 15;
        float4 v = ((const float4*)entity)[i];
        uint2 p;
        p.x = pack_h2(v.x, v.y);
        p.y = pack_h2(v.z, v.w);
        xs2[node * 16 + qq] = p;
    }
    for (int i = gtid; i < E; i += stride)
        atomicAdd(&h[etype[i]], 1);
    __syncthreads();
    if (threadIdx.x < NREL) atomicAdd(&g_cnt[threadIdx.x], h[threadIdx.x]);
}

// ---------- launch 1: TM-aligned prefix + pad-gap fill ----------
__global__ __launch_bounds__(256) void prefix_kernel() {
    __shared__ int soff[NREL + 1], scnt[NREL];
    if (threadIdx.x == 0) {
        int acc = 0;
        for (int r = 0; r < NREL; r++) {
            g_off[r] = acc;
            g_cursor[r] = acc;
            soff[r] = acc;
            scnt[r] = g_cnt[r];
            acc += (g_cnt[r] + TM - 1) & ~(TM - 1);
        }
        g_off[NREL] = acc;
        soff[NREL] = acc;
    }
    __syncthreads();
    for (int r = 0; r < NREL; r++) {
        int start = soff[r] + scnt[r];
        int end   = soff[r + 1];
        for (int i = start + threadIdx.x; i < end; i += blockDim.x)
            g_ids[i] = -1;
    }
}

// ---------- launch 2: relation-sort edge ids ----------
__global__ __launch_bounds__(256) void scatter_kernel(const int* __restrict__ etype, int E) {
    __shared__ int cnt[NREL], base[NREL];
    const int CH = 4096;
    int e0 = blockIdx.x * CH;
    if (threadIdx.x < NREL) cnt[threadIdx.x] = 0;
    __syncthreads();
    for (int i = threadIdx.x; i < CH; i += 256) {
        int e = e0 + i;
        if (e < E) atomicAdd(&cnt[etype[e]], 1);
    }
    __syncthreads();
    if (threadIdx.x < NREL) {
        base[threadIdx.x] = atomicAdd(&g_cursor[threadIdx.x], cnt[threadIdx.x]);
        cnt[threadIdx.x] = 0;
    }
    __syncthreads();
    for (int i = threadIdx.x; i < CH; i += 256) {
        int e = e0 + i;
        if (e < E) {
            int r = etype[e];
            int p = base[r] + atomicAdd(&cnt[r], 1);
            g_ids[p] = e;
        }
    }
}

// ---------- launch 3: edge kernel — fp16 mma; compute warps also scatter ----------
// Warps 0-7 compute: mma (rows (w&3)*32, cols (w>>2)*32) + epilogue + scatter of
// rows (w&3)*32 + (w>>2)*16 .. +15. Warps 8-11: gather only.
__global__ __launch_bounds__(384, 2)
void edge_kernel(const float* __restrict__ entity, const float* __restrict__ rel,
                 const float* __restrict__ W_R,
                 const int* __restrict__ src, const int* __restrict__ dst)
{
    extern __shared__ char smc[];
    const uint32_t sbase = smem_u32(smc);
    float* sRe  = (float*)(smc + SM_RE);
    float* sAtt = (float*)(smc + SM_ATT);
    int*   sSrc = (int*)(smc + SM_SRC);
    int*   sDst = (int*)(smc + SM_DST);
    int*   sOff = (int*)(smc + SM_OFF);

    const int tid  = threadIdx.x;
    const int wid  = tid >> 5;
    const int lane = tid & 31;

    if (tid < NREL + 1) sOff[tid] = g_off[tid];
    __syncthreads();
    const int T   = sOff[NREL] >> 7;
    const int per = (T + gridDim.x - 1) / gridDim.x;
    const int t0g = blockIdx.x * per;
    const int n   = min(T, t0g + per) - t0g;
    if (n <= 0) return;

    auto rel_of = [&](int t) {
        int p0 = (t0g + t) << 7, r = 0;
        while (p0 >= sOff[r + 1]) r++;
        return r;
    };

    if (wid < 8) {
        // ================= compute role (mma + epilogue + scatter) =================
        const int mgrp = wid & 3;
        const int nh   = wid >> 2;
        const int wrow = mgrp * 32;
        const uint32_t Wh = sbase + SM_W0;
        const int srow0 = mgrp * 32 + nh * 16;   // scatter rows srow0..srow0+15
        const int h     = lane >> 4;
        const int q     = lane & 15;
        int r_cur = -1;

        for (int lt = 0; lt < n; lt++) {
            const int b = lt & 1;
            BAR_SYNC(1 + b);                // wait A[b] full

            int r = rel_of(lt);
            if (r != r_cur) {
                r_cur = r;
                const float* wr = W_R + (size_t)r * 4096;
                for (int i = tid; i < 4096; i += 256) {
                    int k = i >> 6, nn = i & 63;
                    __half h0 = __float2half_rn(wr[i]);
                    int off = k * 128 + (((nn >> 3) ^ (k & 7)) << 4) + (nn & 7) * 2;
                    *(__half*)(smc + SM_W0 + off) = h0;
                }
                if (tid < 64) sRe[tid] = rel[r * 64 + tid];
                BAR_SYNC_C(5);
            }

            const uint32_t Ah = sbase + SM_A + b * 16384;

            float acc[2][4][4];
            #pragma unroll
            for (int mb = 0; mb < 2; mb++)
                #pragma unroll
                for (int nt = 0; nt < 4; nt++)
                    #pragma unroll
                    for (int c = 0; c < 4; c++) acc[mb][nt][c] = 0.f;

            #pragma unroll
            for (int kt = 0; kt < 4; kt++) {
                uint32_t a0[4], a1[4];
                ldm_a(a0, Ah, wrow, kt, lane);
                ldm_a(a1, Ah, wrow + 16, kt, lane);
                #pragma unroll
                for (int p = 0; p < 2; p++) {
                    int np = nh * 2 + p;
                    uint32_t bh[4];
                    ldm_b(bh, Wh, np, kt, lane);
                    mma16816(acc[0][2 * p],     a0, bh[0], bh[1]);
                    mma16816(acc[1][2 * p],     a1, bh[0], bh[1]);
                    mma16816(acc[0][2 * p + 1], a0, bh[2], bh[3]);
                    mma16816(acc[1][2 * p + 1], a1, bh[2], bh[3]);
                }
            }

            // epilogue: partial att over this warp's 32 cols, shfl-reduced
            float reg_re[8];
            #pragma unroll
            for (int nt = 0; nt < 4; nt++) {
                reg_re[2 * nt]     = sRe[nh * 32 + nt * 8 + 2 * (lane & 3)];
                reg_re[2 * nt + 1] = sRe[nh * 32 + nt * 8 + 2 * (lane & 3) + 1];
            }
            float* sAb = sAtt + b * 256;
            #pragma unroll
            for (int mb = 0; mb < 2; mb++) {
                #pragma unroll
                for (int hh = 0; hh < 2; hh++) {
                    float part = 0.f;
                    #pragma unroll
                    for (int nt = 0; nt < 4; nt++) {
                        float m0 = acc[mb][nt][hh * 2 + 0];
                        float m1 = acc[mb][nt][hh * 2 + 1];
                        part += m0 * tanh_f(m0 + reg_re[2 * nt]);
                        part += m1 * tanh_f(m1 + reg_re[2 * nt + 1]);
                    }
                    part += __shfl_xor_sync(0xffffffffu, part, 1);
                    part += __shfl_xor_sync(0xffffffffu, part, 2);
                    if ((lane & 3) == 0) {
                        int row = wrow + mb * 16 + hh * 8 + (lane >> 2);
                        sAb[row * 2 + nh] = part;
                    }
                }
            }
            BAR_SYNC_C(6);                  // all compute: sAtt[b] complete

            // scatter this warp's 16 rows (2 rows per iteration)
            {
                const char* ah = smc + SM_A + b * 16384;
                const int* sD = sDst + b * 128;
                #pragma unroll
                for (int i = 0; i < 8; i++) {
                    int row = srow0 + 2 * i + h;
                    int d = sD[row];
                    if (d >= 0) {
                        float a = sAb[row * 2 + 0] + sAb[row * 2 + 1];
                        int off = row * 128 + (((q >> 1) ^ (row & 7)) << 4) + (q & 1) * 8;
                        uint2 p = *(const uint2*)(ah + off);
                        red_add_v4(g_neighbor + (size_t)d * DIM + q * 4,
                                   a * h_lo(p.x), a * h_hi(p.x),
                                   a * h_lo(p.y), a * h_hi(p.y));
                    }
                }
            }
            BAR_ARRIVE(3 + b);              // A[b] free for re-gather
        }
    } else {
        // ================= mem role (gather only) =================
        const int wbase = (wid - 8) << 5;

        auto do_gather = [&](int lt, int b) {
            char* ah = smc + SM_A + b * 16384;
            int* sS = sSrc + b * 128;
            int* sD = sDst + b * 128;
            const int p0 = (t0g + lt) << 7;
            int mrow = wbase + lane;
            int id = g_ids[p0 + mrow];
            int s = -1, d = -1;
            if (id >= 0) { s = src[id]; d = dst[id]; }
            sS[mrow] = s;
            sD[mrow] = d;
            __syncwarp();
            const int c = lane & 7;
            #pragma unroll
            for (int i = 0; i < 8; i++) {
                int row = wbase + 4 * i + (lane >> 3);
                int ss = sS[row];
                uint4 v = make_uint4(0u, 0u, 0u, 0u);
                if (ss >= 0) v = g_xs[ss * 8 + c];
                *(uint4*)(ah + row * 128 + ((c ^ (row & 7)) << 4)) = v;
            }
        };

        do_gather(0, 0);
        BAR_ARRIVE(1);
        if (n > 1) {
            do_gather(1, 1);
            BAR_ARRIVE(2);
        }
        for (int lt = 0; lt + 2 < n; lt++) {
            const int b = lt & 1;
            BAR_SYNC(3 + b);                // wait A[b] free (compute done scattering)
            do_gather(lt + 2, b);
            BAR_ARRIVE(1 + b);              // A[b] full
        }
    }
}

// ---------- launch 4: combine (scalar f32x2, unchanged) ----------
__global__ __launch_bounds__(128, 1) void combine_kernel(
    const float* __restrict__ entity, const float* __restrict__ W_w,
    const float* __restrict__ W_b, float* __restrict__ out, int n_nodes)
{
    extern __shared__ float smem[];
    float* sW = smem;
    float* sX = sW + 8704;
    float* sB = sX + 128 * 132;

    const int tid = threadIdx.x;
    const int n0  = blockIdx.x * 128;

    for (int i = tid; i < 8192; i += 128) {
        int j = i >> 7, k = i & 127;
        sW[k * 68 + j] = W_w[i];
    }
    if (tid < 64) sB[tid] = W_b[tid];

    {
        int n = n0 + tid;
        if (n < n_nodes) {
            const float4* hp = (const float4*)(entity + (size_t)n * DIM);
            const float4* np = (const float4*)(g_neighbor + (size_t)n * DIM);
            #pragma unroll
            for (int qq = 0; qq < 16; qq++) {
                float4 v = hp[qq];
                sX[(4 * qq + 0) * 132 + tid] = v.x;
                sX[(4 * qq + 1) * 132 + tid] = v.y;
                sX[(4 * qq + 2) * 132 + tid] = v.z;
                sX[(4 * qq + 3) * 132 + tid] = v.w;
                float4 w = np[qq];
                sX[(64 + 4 * qq + 0) * 132 + tid] = w.x;
                sX[(64 + 4 * qq + 1) * 132 + tid] = w.y;
                sX[(64 + 4 * qq + 2) * 132 + tid] = w.z;
                sX[(64 + 4 * qq + 3) * 132 + tid] = w.w;
            }
        }
    }
    __syncthreads();

    const int ti = tid & 15;
    const int tj = tid >> 4;

    unsigned long long acc[4][8];
    #pragma unroll
    for (int p = 0; p < 4; p++)
        #pragma unroll
        for (int c = 0; c < 8; c++) acc[p][c] = 0ull;

    const float* xb = sX + ti * 8;
    const float* wb = sW + tj * 8;
    #pragma unroll 8
    for (int k = 0; k < 128; k++) {
        float4 a0 = *(const float4*)(xb + k * 132);
        float4 a1 = *(const float4*)(xb + k * 132 + 4);
        float4 w0 = *(const float4*)(wb + k * 68);
        float4 w1 = *(const float4*)(wb + k * 68 + 4);
        unsigned long long A[4] = { pack2(a0.x, a0.y), pack2(a0.z, a0.w),
                                    pack2(a1.x, a1.y), pack2(a1.z, a1.w) };
        unsigned long long B[8] = { pack2(w0.x, w0.x), pack2(w0.y, w0.y),
                                    pack2(w0.z, w0.z), pack2(w0.w, w0.w),
                                    pack2(w1.x, w1.x), pack2(w1.y, w1.y),
                                    pack2(w1.z, w1.z), pack2(w1.w, w1.w) };
        #pragma unroll
        for (int p = 0; p < 4; p++)
            #pragma unroll
            for (int c = 0; c < 8; c++) fma2(acc[p][c], A[p], B[c]);
    }

    float bcol[8];
    #pragma unroll
    for (int c = 0; c < 8; c++) bcol[c] = sB[tj * 8 + c];

    #pragma unroll
    for (int p = 0; p < 4; p++) {
        int r0 = n0 + ti * 8 + 2 * p;
        float v0[8], v1[8];
        #pragma unroll
        for (int c = 0; c < 8; c++) {
            float2 m = unpack2(acc[p][c]);
            float x0 = m.x + bcol[c];
            float x1 = m.y + bcol[c];
            v0[c] = (x0 > 0.f) ? x0 : 0.01f * x0;
            v1[c] = (x1 > 0.f) ? x1 : 0.01f * x1;
        }
        if (r0 < n_nodes) {
            const float4* hp = (const float4*)(entity + (size_t)r0 * DIM);
            float4 e0 = hp[tj * 2], e1 = hp[tj * 2 + 1];
            float4* op = (float4*)(out + (size_t)r0 * DIM + tj * 8);
            op[0] = make_float4(v0[0] + e0.x, v0[1] + e0.y, v0[2] + e0.z, v0[3] + e0.w);
            op[1] = make_float4(v0[4] + e1.x, v0[5] + e1.y, v0[6] + e1.z, v0[7] + e1.w);
        }
        if (r0 + 1 < n_nodes) {
            const float4* hp = (const float4*)(entity + (size_t)(r0 + 1) * DIM);
            float4 e0 = hp[tj * 2], e1 = hp[tj * 2 + 1];
            float4* op = (float4*)(out + (size_t)(r0 + 1) * DIM + tj * 8);
            op[0] = make_float4(v1[0] + e0.x, v1[1] + e0.y, v1[2] + e0.z, v1[3] + e0.w);
            op[1] = make_float4(v1[4] + e1.x, v1[5] + e1.y, v1[6] + e1.z, v1[7] + e1.w);
        }
    }
}

extern "C" void kernel_launch(void* const* d_in, const int* in_sizes, int n_in,
                              void* d_out, int out_size)
{
    const float* entity = (const float*)d_in[0];
    const float* rel    = (const float*)d_in[1];
    const float* W_R    = (const float*)d_in[2];
    const float* W_w    = (const float*)d_in[3];
    const float* W_b    = (const float*)d_in[4];
    const int*   src    = (const int*)d_in[5];
    const int*   dst    = (const int*)d_in[6];
    const int*   etype  = (const int*)d_in[7];

    const int E = in_sizes[5];
    const int n = in_sizes[0] / DIM;

    const size_t smem_comb = (8704 + 128 * 132 + 64) * sizeof(float);
    cudaFuncSetAttribute(edge_kernel, cudaFuncAttributeMaxDynamicSharedMemorySize, SM_EDGE_TOTAL);
    cudaFuncSetAttribute(combine_kernel, cudaFuncAttributeMaxDynamicSharedMemorySize, (int)smem_comb);

    int n4neigh = n * DIM / 4;
    int nf4     = n * DIM / 4;

    init_hist_kernel<<<1024, 256>>>(entity, etype, E, n4neigh, nf4);         // launch 0
    prefix_kernel<<<1, 256>>>();                                             // launch 1
    scatter_kernel<<<(E + 4095) / 4096, 256>>>(etype, E);                    // launch 2
    edge_kernel<<<296, 384, SM_EDGE_TOTAL>>>(entity, rel, W_R, src, dst);    // launch 3 (profiled)
    combine_kernel<<<(n + 127) / 128, 128, smem_comb>>>(entity, W_w, W_b, (float*)d_out, n);  // launch 4
}

// round 17
// speedup vs baseline: 1.3797x; 1.3797x over previous
#include <cuda_runtime.h>
#include <cuda_fp16.h>
#include <cstdint>

#define NN 100000
#define DIM 64
#define NREL 16
#define EMAX 1000000
#define TM 128
#define IDS_CAP (EMAX + NREL * TM)

__device__ float g_neighbor[NN * DIM];
__device__ int   g_ids[IDS_CAP];
__device__ int   g_cnt[NREL];
__device__ int   g_off[NREL + 1];
__device__ int   g_cursor[NREL];
__device__ uint4 g_xs[NN * 8];         // per node: 64 fp16 (128B)

// ---------------- smem byte map (edge kernel) ----------------
#define SM_W0   0                      // W fp16 [64k][64n] swizzled (8192)
#define SM_A    8192                   // A: buf0, buf1 fp16 (2 x 16384)
#define SM_RE   40960                  // 64 f32
#define SM_ATT  41216                  // 2 x 128 x 2 f32
#define SM_SRC  43264                  // 2 x 128 int
#define SM_DST  44288                  // 2 x 128 int
#define SM_OFF  45312                  // 17 int (+pad)
#define SM_EDGE_TOTAL 45440

// named barriers (384 threads):
//   1,2 = A-full[b]   (mem 128 arrive, compute 256 sync)
//   3,4 = ATT[b]      (compute 256 arrive, mem 128 sync)
//   5,6 = CS-done[b]  (compute 256 arrive, mem 128 sync)
//   7   = W reload    (compute-internal, 256)
//   8   = epi done    (compute-internal, 256)
#define BAR_SYNC(id)   asm volatile("bar.sync %0, 384;"   :: "r"(id) : "memory")
#define BAR_ARRIVE(id) asm volatile("bar.arrive %0, 384;" :: "r"(id) : "memory")
#define BAR_SYNC_C(id) asm volatile("bar.sync %0, 256;"   :: "r"(id) : "memory")

static __device__ __forceinline__ uint32_t smem_u32(const void* p) {
    uint32_t a;
    asm("{ .reg .u64 t; cvta.to.shared.u64 t, %1; cvt.u32.u64 %0, t; }" : "=r"(a) : "l"(p));
    return a;
}

// ---------- mma.sync / ldmatrix helpers ----------
__device__ __forceinline__ void ldm_a(uint32_t* r, uint32_t base, int m0, int kt, int lane) {
    int row   = m0 + (lane & 15);
    int chunk = (kt << 1) + (lane >> 4);
    uint32_t addr = base + row * 128 + ((chunk ^ (row & 7)) << 4);
    asm volatile("ldmatrix.sync.aligned.m8n8.x4.shared.b16 {%0,%1,%2,%3}, [%4];"
                 : "=r"(r[0]), "=r"(r[1]), "=r"(r[2]), "=r"(r[3]) : "r"(addr));
}
__device__ __forceinline__ void ldm_b(uint32_t* r, uint32_t base, int np, int kt, int lane) {
    int g = lane >> 3;
    int k = (kt << 4) + ((g & 1) << 3) + (lane & 7);
    int nchunk = (np << 1) + (g >> 1);
    uint32_t addr = base + k * 128 + ((nchunk ^ (k & 7)) << 4);
    asm volatile("ldmatrix.sync.aligned.m8n8.x4.trans.shared.b16 {%0,%1,%2,%3}, [%4];"
                 : "=r"(r[0]), "=r"(r[1]), "=r"(r[2]), "=r"(r[3]) : "r"(addr));
}
__device__ __forceinline__ void mma16816(float* d, const uint32_t* a, uint32_t b0, uint32_t b1) {
    asm volatile("mma.sync.aligned.m16n8k16.row.col.f32.f16.f16.f32 "
                 "{%0,%1,%2,%3}, {%4,%5,%6,%7}, {%8,%9}, {%0,%1,%2,%3};"
                 : "+f"(d[0]), "+f"(d[1]), "+f"(d[2]), "+f"(d[3])
                 : "r"(a[0]), "r"(a[1]), "r"(a[2]), "r"(a[3]), "r"(b0), "r"(b1));
}

// ---------- misc helpers ----------
__device__ __forceinline__ void fma2(unsigned long long& d, unsigned long long a, unsigned long long b) {
    asm("fma.rn.f32x2 %0, %1, %2, %0;" : "+l"(d) : "l"(a), "l"(b));
}
__device__ __forceinline__ float2 unpack2(unsigned long long v) {
    float2 r;
    r.x = __uint_as_float((unsigned)(v & 0xffffffffull));
    r.y = __uint_as_float((unsigned)(v >> 32));
    return r;
}
__device__ __forceinline__ unsigned long long pack2(float x, float y) {
    unsigned long long r;
    asm("mov.b64 %0, {%1, %2};" : "=l"(r) : "f"(x), "f"(y));
    return r;
}
__device__ __forceinline__ float tanh_f(float x) {
    float y;
    asm("tanh.approx.f32 %0, %1;" : "=f"(y) : "f"(x));
    return y;
}
__device__ __forceinline__ void red_add_v4(float* addr, float a, float b, float c, float d) {
    asm volatile("red.global.add.v4.f32 [%0], {%1, %2, %3, %4};"
                 :: "l"(addr), "f"(a), "f"(b), "f"(c), "f"(d) : "memory");
}
__device__ __forceinline__ uint32_t pack_h2(float a, float b) {
    unsigned short s0 = __half_as_ushort(__float2half_rn(a));
    unsigned short s1 = __half_as_ushort(__float2half_rn(b));
    return (uint32_t)s0 | ((uint32_t)s1 << 16);
}
__device__ __forceinline__ float h_lo(uint32_t u) {
    return __half2float(__ushort_as_half((unsigned short)(u & 0xffff)));
}
__device__ __forceinline__ float h_hi(uint32_t u) {
    return __half2float(__ushort_as_half((unsigned short)(u >> 16)));
}

// ---------- launch 0: init + histogram + entity fp16 table ----------
__global__ __launch_bounds__(256) void init_hist_kernel(const float* __restrict__ entity,
                                                        const int* __restrict__ etype,
                                                        int E, int n4neigh, int nf4) {
    __shared__ int h[NREL];
    if (threadIdx.x < NREL) h[threadIdx.x] = 0;
    __syncthreads();
    int gtid = blockIdx.x * blockDim.x + threadIdx.x;
    int stride = gridDim.x * blockDim.x;
    if (gtid < NREL) g_cnt[gtid] = 0;
    for (int i = gtid; i < n4neigh; i += stride)
        ((float4*)g_neighbor)[i] = make_float4(0.f, 0.f, 0.f, 0.f);
    uint2* xs2 = (uint2*)g_xs;
    for (int i = gtid; i < nf4; i += stride) {
        int node = i >> 4, qq = i & 15;
        float4 v = ((const float4*)entity)[i];
        uint2 p;
        p.x = pack_h2(v.x, v.y);
        p.y = pack_h2(v.z, v.w);
        xs2[node * 16 + qq] = p;
    }
    for (int i = gtid; i < E; i += stride)
        atomicAdd(&h[etype[i]], 1);
    __syncthreads();
    if (threadIdx.x < NREL) atomicAdd(&g_cnt[threadIdx.x], h[threadIdx.x]);
}

// ---------- launch 1: TM-aligned prefix + pad-gap fill ----------
__global__ __launch_bounds__(256) void prefix_kernel() {
    __shared__ int soff[NREL + 1], scnt[NREL];
    if (threadIdx.x == 0) {
        int acc = 0;
        for (int r = 0; r < NREL; r++) {
            g_off[r] = acc;
            g_cursor[r] = acc;
            soff[r] = acc;
            scnt[r] = g_cnt[r];
            acc += (g_cnt[r] + TM - 1) & ~(TM - 1);
        }
        g_off[NREL] = acc;
        soff[NREL] = acc;
    }
    __syncthreads();
    for (int r = 0; r < NREL; r++) {
        int start = soff[r] + scnt[r];
        int end   = soff[r + 1];
        for (int i = start + threadIdx.x; i < end; i += blockDim.x)
            g_ids[i] = -1;
    }
}

// ---------- launch 2: relation-sort edge ids ----------
__global__ __launch_bounds__(256) void scatter_kernel(const int* __restrict__ etype, int E) {
    __shared__ int cnt[NREL], base[NREL];
    const int CH = 4096;
    int e0 = blockIdx.x * CH;
    if (threadIdx.x < NREL) cnt[threadIdx.x] = 0;
    __syncthreads();
    for (int i = threadIdx.x; i < CH; i += 256) {
        int e = e0 + i;
        if (e < E) atomicAdd(&cnt[etype[e]], 1);
    }
    __syncthreads();
    if (threadIdx.x < NREL) {
        base[threadIdx.x] = atomicAdd(&g_cursor[threadIdx.x], cnt[threadIdx.x]);
        cnt[threadIdx.x] = 0;
    }
    __syncthreads();
    for (int i = threadIdx.x; i < CH; i += 256) {
        int e = e0 + i;
        if (e < E) {
            int r = etype[e];
            int p = base[r] + atomicAdd(&cnt[r], 1);
            g_ids[p] = e;
        }
    }
}

// ---------- launch 3: edge kernel — fp16 mma; scatter split across all warps ----------
// Warps 0-7 compute: mma + epilogue + scatter rows 64..127 (8 each).
// Warps 8-11 mem: gather + scatter rows 0..63 (16 each).
__global__ __launch_bounds__(384, 2)
void edge_kernel(const float* __restrict__ entity, const float* __restrict__ rel,
                 const float* __restrict__ W_R,
                 const int* __restrict__ src, const int* __restrict__ dst)
{
    extern __shared__ char smc[];
    const uint32_t sbase = smem_u32(smc);
    float* sRe  = (float*)(smc + SM_RE);
    float* sAtt = (float*)(smc + SM_ATT);
    int*   sSrc = (int*)(smc + SM_SRC);
    int*   sDst = (int*)(smc + SM_DST);
    int*   sOff = (int*)(smc + SM_OFF);

    const int tid  = threadIdx.x;
    const int wid  = tid >> 5;
    const int lane = tid & 31;

    if (tid < NREL + 1) sOff[tid] = g_off[tid];
    __syncthreads();
    const int T   = sOff[NREL] >> 7;
    const int per = (T + gridDim.x - 1) / gridDim.x;
    const int t0g = blockIdx.x * per;
    const int n   = min(T, t0g + per) - t0g;
    if (n <= 0) return;

    auto rel_of = [&](int t) {
        int p0 = (t0g + t) << 7, r = 0;
        while (p0 >= sOff[r + 1]) r++;
        return r;
    };

    if (wid < 8) {
        // ============ compute role: mma + epilogue + scatter rows 64..127 ============
        const int mgrp = wid & 3;
        const int nh   = wid >> 2;
        const int wrow = mgrp * 32;
        const uint32_t Wh = sbase + SM_W0;
        const int srow0 = 64 + wid * 8;      // this warp scatters 8 rows
        const int h     = lane >> 4;
        const int q     = lane & 15;
        int r_cur = -1;

        for (int lt = 0; lt < n; lt++) {
            const int b = lt & 1;
            BAR_SYNC(1 + b);                // wait A[b] full

            int r = rel_of(lt);
            if (r != r_cur) {
                r_cur = r;
                const float* wr = W_R + (size_t)r * 4096;
                for (int i = tid; i < 4096; i += 256) {
                    int k = i >> 6, nn = i & 63;
                    __half h0 = __float2half_rn(wr[i]);
                    int off = k * 128 + (((nn >> 3) ^ (k & 7)) << 4) + (nn & 7) * 2;
                    *(__half*)(smc + SM_W0 + off) = h0;
                }
                if (tid < 64) sRe[tid] = rel[r * 64 + tid];
                BAR_SYNC_C(7);
            }

            const uint32_t Ah = sbase + SM_A + b * 16384;

            float acc[2][4][4];
            #pragma unroll
            for (int mb = 0; mb < 2; mb++)
                #pragma unroll
                for (int nt = 0; nt < 4; nt++)
                    #pragma unroll
                    for (int c = 0; c < 4; c++) acc[mb][nt][c] = 0.f;

            #pragma unroll
            for (int kt = 0; kt < 4; kt++) {
                uint32_t a0[4], a1[4];
                ldm_a(a0, Ah, wrow, kt, lane);
                ldm_a(a1, Ah, wrow + 16, kt, lane);
                #pragma unroll
                for (int p = 0; p < 2; p++) {
                    int np = nh * 2 + p;
                    uint32_t bh[4];
                    ldm_b(bh, Wh, np, kt, lane);
                    mma16816(acc[0][2 * p],     a0, bh[0], bh[1]);
                    mma16816(acc[1][2 * p],     a1, bh[0], bh[1]);
                    mma16816(acc[0][2 * p + 1], a0, bh[2], bh[3]);
                    mma16816(acc[1][2 * p + 1], a1, bh[2], bh[3]);
                }
            }

            // epilogue: partial att over this warp's 32 cols, shfl-reduced
            float reg_re[8];
            #pragma unroll
            for (int nt = 0; nt < 4; nt++) {
                reg_re[2 * nt]     = sRe[nh * 32 + nt * 8 + 2 * (lane & 3)];
                reg_re[2 * nt + 1] = sRe[nh * 32 + nt * 8 + 2 * (lane & 3) + 1];
            }
            float* sAb = sAtt + b * 256;
            #pragma unroll
            for (int mb = 0; mb < 2; mb++) {
                #pragma unroll
                for (int hh = 0; hh < 2; hh++) {
                    float part = 0.f;
                    #pragma unroll
                    for (int nt = 0; nt < 4; nt++) {
                        float m0 = acc[mb][nt][hh * 2 + 0];
                        float m1 = acc[mb][nt][hh * 2 + 1];
                        part += m0 * tanh_f(m0 + reg_re[2 * nt]);
                        part += m1 * tanh_f(m1 + reg_re[2 * nt + 1]);
                    }
                    part += __shfl_xor_sync(0xffffffffu, part, 1);
                    part += __shfl_xor_sync(0xffffffffu, part, 2);
                    if ((lane & 3) == 0) {
                        int row = wrow + mb * 16 + hh * 8 + (lane >> 2);
                        sAb[row * 2 + nh] = part;
                    }
                }
            }
            BAR_ARRIVE(3 + b);              // ATT[b] ready (for mem warps)
            BAR_SYNC_C(8);                  // all compute sAtt writes visible

            // scatter this warp's 8 rows (2 per iteration)
            {
                const char* ah = smc + SM_A + b * 16384;
                const int* sD = sDst + b * 128;
                #pragma unroll
                for (int i = 0; i < 4; i++) {
                    int row = srow0 + 2 * i + h;
                    int d = sD[row];
                    if (d >= 0) {
                        float a = sAb[row * 2 + 0] + sAb[row * 2 + 1];
                        int off = row * 128 + (((q >> 1) ^ (row & 7)) << 4) + (q & 1) * 8;
                        uint2 p = *(const uint2*)(ah + off);
                        red_add_v4(g_neighbor + (size_t)d * DIM + q * 4,
                                   a * h_lo(p.x), a * h_hi(p.x),
                                   a * h_lo(p.y), a * h_hi(p.y));
                    }
                }
            }
            BAR_ARRIVE(5 + b);              // compute-scatter[b] done
        }
    } else {
        // ============ mem role: gather + scatter rows 0..63 ============
        const int mw    = wid - 8;
        const int wbase = mw << 5;           // gather rows
        const int srow0 = mw * 16;           // scatter rows (16 each)
        const int h     = lane >> 4;
        const int q     = lane & 15;

        auto do_gather = [&](int lt, int b) {
            char* ah = smc + SM_A + b * 16384;
            int* sS = sSrc + b * 128;
            int* sD = sDst + b * 128;
            const int p0 = (t0g + lt) << 7;
            int mrow = wbase + lane;
            int id = g_ids[p0 + mrow];
            int s = -1, d = -1;
            if (id >= 0) { s = src[id]; d = dst[id]; }
            sS[mrow] = s;
            sD[mrow] = d;
            __syncwarp();
            const int c = lane & 7;
            #pragma unroll
            for (int i = 0; i < 8; i++) {
                int row = wbase + 4 * i + (lane >> 3);
                int ss = sS[row];
                uint4 v = make_uint4(0u, 0u, 0u, 0u);
                if (ss >= 0) v = g_xs[ss * 8 + c];
                *(uint4*)(ah + row * 128 + ((c ^ (row & 7)) << 4)) = v;
            }
        };

        auto do_scatter_half = [&](int b) {
            const char* ah = smc + SM_A + b * 16384;
            const float* sAb = sAtt + b * 256;
            const int* sD = sDst + b * 128;
            #pragma unroll
            for (int i = 0; i < 8; i++) {
                int row = srow0 + 2 * i + h;
                int d = sD[row];
                if (d >= 0) {
                    float a = sAb[row * 2 + 0] + sAb[row * 2 + 1];
                    int off = row * 128 + (((q >> 1) ^ (row & 7)) << 4) + (q & 1) * 8;
                    uint2 p = *(const uint2*)(ah + off);
                    red_add_v4(g_neighbor + (size_t)d * DIM + q * 4,
                               a * h_lo(p.x), a * h_hi(p.x),
                               a * h_lo(p.y), a * h_hi(p.y));
                }
            }
        };

        do_gather(0, 0);
        BAR_ARRIVE(1);
        if (n > 1) {
            do_gather(1, 1);
            BAR_ARRIVE(2);
        }
        for (int lt = 0; lt < n; lt++) {
            const int b = lt & 1;
            BAR_SYNC(3 + b);                // ATT[b] ready
            do_scatter_half(b);
            BAR_SYNC(5 + b);                // compute-scatter[b] done (A[b] free)
            if (lt + 2 < n) {
                do_gather(lt + 2, b);
                BAR_ARRIVE(1 + b);          // A[b] full
            }
        }
    }
}

// ---------- launch 4: combine (scalar f32x2, unchanged) ----------
__global__ __launch_bounds__(128, 1) void combine_kernel(
    const float* __restrict__ entity, const float* __restrict__ W_w,
    const float* __restrict__ W_b, float* __restrict__ out, int n_nodes)
{
    extern __shared__ float smem[];
    float* sW = smem;
    float* sX = sW + 8704;
    float* sB = sX + 128 * 132;

    const int tid = threadIdx.x;
    const int n0  = blockIdx.x * 128;

    for (int i = tid; i < 8192; i += 128) {
        int j = i >> 7, k = i & 127;
        sW[k * 68 + j] = W_w[i];
    }
    if (tid < 64) sB[tid] = W_b[tid];

    {
        int n = n0 + tid;
        if (n < n_nodes) {
            const float4* hp = (const float4*)(entity + (size_t)n * DIM);
            const float4* np = (const float4*)(g_neighbor + (size_t)n * DIM);
            #pragma unroll
            for (int qq = 0; qq < 16; qq++) {
                float4 v = hp[qq];
                sX[(4 * qq + 0) * 132 + tid] = v.x;
                sX[(4 * qq + 1) * 132 + tid] = v.y;
                sX[(4 * qq + 2) * 132 + tid] = v.z;
                sX[(4 * qq + 3) * 132 + tid] = v.w;
                float4 w = np[qq];
                sX[(64 + 4 * qq + 0) * 132 + tid] = w.x;
                sX[(64 + 4 * qq + 1) * 132 + tid] = w.y;
                sX[(64 + 4 * qq + 2) * 132 + tid] = w.z;
                sX[(64 + 4 * qq + 3) * 132 + tid] = w.w;
            }
        }
    }
    __syncthreads();

    const int ti = tid & 15;
    const int tj = tid >> 4;

    unsigned long long acc[4][8];
    #pragma unroll
    for (int p = 0; p < 4; p++)
        #pragma unroll
        for (int c = 0; c < 8; c++) acc[p][c] = 0ull;

    const float* xb = sX + ti * 8;
    const float* wb = sW + tj * 8;
    #pragma unroll 8
    for (int k = 0; k < 128; k++) {
        float4 a0 = *(const float4*)(xb + k * 132);
        float4 a1 = *(const float4*)(xb + k * 132 + 4);
        float4 w0 = *(const float4*)(wb + k * 68);
        float4 w1 = *(const float4*)(wb + k * 68 + 4);
        unsigned long long A[4] = { pack2(a0.x, a0.y), pack2(a0.z, a0.w),
                                    pack2(a1.x, a1.y), pack2(a1.z, a1.w) };
        unsigned long long B[8] = { pack2(w0.x, w0.x), pack2(w0.y, w0.y),
                                    pack2(w0.z, w0.z), pack2(w0.w, w0.w),
                                    pack2(w1.x, w1.x), pack2(w1.y, w1.y),
                                    pack2(w1.z, w1.z), pack2(w1.w, w1.w) };
        #pragma unroll
        for (int p = 0; p < 4; p++)
            #pragma unroll
            for (int c = 0; c < 8; c++) fma2(acc[p][c], A[p], B[c]);
    }

    float bcol[8];
    #pragma unroll
    for (int c = 0; c < 8; c++) bcol[c] = sB[tj * 8 + c];

    #pragma unroll
    for (int p = 0; p < 4; p++) {
        int r0 = n0 + ti * 8 + 2 * p;
        float v0[8], v1[8];
        #pragma unroll
        for (int c = 0; c < 8; c++) {
            float2 m = unpack2(acc[p][c]);
            float x0 = m.x + bcol[c];
            float x1 = m.y + bcol[c];
            v0[c] = (x0 > 0.f) ? x0 : 0.01f * x0;
            v1[c] = (x1 > 0.f) ? x1 : 0.01f * x1;
        }
        if (r0 < n_nodes) {
            const float4* hp = (const float4*)(entity + (size_t)r0 * DIM);
            float4 e0 = hp[tj * 2], e1 = hp[tj * 2 + 1];
            float4* op = (float4*)(out + (size_t)r0 * DIM + tj * 8);
            op[0] = make_float4(v0[0] + e0.x, v0[1] + e0.y, v0[2] + e0.z, v0[3] + e0.w);
            op[1] = make_float4(v0[4] + e1.x, v0[5] + e1.y, v0[6] + e1.z, v0[7] + e1.w);
        }
        if (r0 + 1 < n_nodes) {
            const float4* hp = (const float4*)(entity + (size_t)(r0 + 1) * DIM);
            float4 e0 = hp[tj * 2], e1 = hp[tj * 2 + 1];
            float4* op = (float4*)(out + (size_t)(r0 + 1) * DIM + tj * 8);
            op[0] = make_float4(v1[0] + e0.x, v1[1] + e0.y, v1[2] + e0.z, v1[3] + e0.w);
            op[1] = make_float4(v1[4] + e1.x, v1[5] + e1.y, v1[6] + e1.z, v1[7] + e1.w);
        }
    }
}

extern "C" void kernel_launch(void* const* d_in, const int* in_sizes, int n_in,
                              void* d_out, int out_size)
{
    const float* entity = (const float*)d_in[0];
    const float* rel    = (const float*)d_in[1];
    const float* W_R    = (const float*)d_in[2];
    const float* W_w    = (const float*)d_in[3];
    const float* W_b    = (const float*)d_in[4];
    const int*   src    = (const int*)d_in[5];
    const int*   dst    = (const int*)d_in[6];
    const int*   etype  = (const int*)d_in[7];

    const int E = in_sizes[5];
    const int n = in_sizes[0] / DIM;

    const size_t smem_comb = (8704 + 128 * 132 + 64) * sizeof(float);
    cudaFuncSetAttribute(edge_kernel, cudaFuncAttributeMaxDynamicSharedMemorySize, SM_EDGE_TOTAL);
    cudaFuncSetAttribute(combine_kernel, cudaFuncAttributeMaxDynamicSharedMemorySize, (int)smem_comb);

    int n4neigh = n * DIM / 4;
    int nf4     = n * DIM / 4;

    init_hist_kernel<<<1024, 256>>>(entity, etype, E, n4neigh, nf4);         // launch 0
    prefix_kernel<<<1, 256>>>();                                             // launch 1
    scatter_kernel<<<(E + 4095) / 4096, 256>>>(etype, E);                    // launch 2
    edge_kernel<<<296, 384, SM_EDGE_TOTAL>>>(entity, rel, W_R, src, dst);    // launch 3 (profiled)
    combine_kernel<<<(n + 127) / 128, 128, smem_comb>>>(entity, W_w, W_b, (float*)d_out, n);  // launch 4
}